// round 15
// baseline (speedup 1.0000x reference)
#include <cuda_runtime.h>
#include <cstdint>

#define IDIM 128
#define HDIM 256
#define ODIM 16
#define MAXB 65536

// Static device scratch. Padded one h-row for phase2's unconditional prefetch.
__device__ unsigned g_masks[(size_t)(HDIM + 1) * MAXB];    // 30-bit spike masks, [h][b]

// ---------------------------------------------------------------------------
// XLA EmitFastTanh, ptxas-contracted (confirmed bit-exact R12-R14).
// ---------------------------------------------------------------------------
__device__ __forceinline__ float xla_tanh(float x) {
    const float kClamp = 7.90531110763549805f;
    float ax = fabsf(x);
    float xc = fmaxf(-kClamp, fminf(kClamp, x));
    float x2 = __fmul_rn(xc, xc);
    float p = __fmaf_rn(x2, -2.76076847742355e-16f, 2.00018790482477e-13f);
    p = __fmaf_rn(x2, p, -8.60467152213735e-11f);
    p = __fmaf_rn(x2, p, 5.12229709037114e-08f);
    p = __fmaf_rn(x2, p, 1.48572235717979e-05f);
    p = __fmaf_rn(x2, p, 6.37261928875436e-04f);
    p = __fmaf_rn(x2, p, 4.89352455891786e-03f);
    float num = __fmul_rn(xc, p);
    float q = __fmaf_rn(x2, 1.19825839466702e-06f, 1.18534705686654e-04f);
    q = __fmaf_rn(x2, q, 2.26843463243900e-03f);
    q = __fmaf_rn(x2, q, 4.89352518554385e-03f);
    float r = __fdiv_rn(num, q);
    return (ax < 0.0004f) ? x : r;
}

__device__ __forceinline__ float leaky_update(float mem, float c, float r) {
    return __fsub_rn(__fmaf_rn(0.95f, mem, c), r);
}

__device__ __forceinline__ float norm_x(float v) {
    const float kRecip3 = 1.0f / 3.0f;   // 0x3EAAAAAB
    return __fmul_rn(fminf(3.0f, fmaxf(-3.0f, v)), kRecip3);
}

__device__ __forceinline__ void fma2(unsigned long long& d, unsigned long long a,
                                     unsigned long long b) {
    asm("fma.rn.f32x2 %0, %1, %2, %0;" : "+l"(d) : "l"(a), "l"(b));
}
__device__ __forceinline__ unsigned long long dup2(float a) {
    unsigned long long r;
    asm("mov.b64 %0, {%1, %1};" : "=l"(r) : "f"(a));
    return r;
}
__device__ __forceinline__ float2 unpack2(unsigned long long v) {
    float2 r;
    asm("mov.b64 {%0, %1}, %2;" : "=f"(r.x), "=f"(r.y) : "l"(v));
    return r;
}

// Predicated packed FMA accumulate on the FMA pipe: acc[j] += w[j]*1.0 iff bit.
// Bit-exact vs reference fma(spike, w, acc): spike=1 -> rn(w+acc) identical;
// spike=0 -> acc unchanged (reference adds +-0, acc never -0).
#define PFMA4(a0, a1, a2, a3, w0, w1, w2, w3, one2, bit)                    \
    asm("{ .reg .pred p; setp.ne.u32 p, %9, 0;\n\t"                         \
        "@p fma.rn.f32x2 %0, %4, %8, %0;\n\t"                               \
        "@p fma.rn.f32x2 %1, %5, %8, %1;\n\t"                               \
        "@p fma.rn.f32x2 %2, %6, %8, %2;\n\t"                               \
        "@p fma.rn.f32x2 %3, %7, %8, %3;\n}"                                \
        : "+l"(a0), "+l"(a1), "+l"(a2), "+l"(a3)                            \
        : "l"(w0), "l"(w1), "l"(w2), "l"(w3), "l"(one2), "r"(bit))

// ---------------------------------------------------------------------------
// Phase 1 (unchanged from R14, bit-exact): tanh(w1)->smem transposed; cur1
// GEMM (f32x2 h-pairs, per-lane ascending-k fma); mem1 recursion -> masks.
// CTA: 512 thr, 128 samples x 256 h; thread tile 8 samples x 4 h-pairs.
// ---------------------------------------------------------------------------
#define W1P 260
#define XP  132
#define P1_SMEM_BYTES ((128 * W1P + 128 * XP) * 4)   // 200704 B

__global__ void __launch_bounds__(512, 1) phase1_kernel(const float* __restrict__ x,
                                                        const float* __restrict__ w1,
                                                        int B, int T) {
    extern __shared__ float sm[];
    float* w1s = sm;                    // [k][h], pitch W1P
    float* xs  = sm + 128 * W1P;        // [s][k], pitch XP
    int tid = threadIdx.x;
    int b0 = blockIdx.x * 128;

    for (int idx = tid; idx < (HDIM * IDIM) / 4; idx += 512) {
        int h = idx >> 5;
        int k4 = (idx & 31) << 2;
        float4 v = *(const float4*)&w1[h * IDIM + k4];
        w1s[(k4 + 0) * W1P + h] = xla_tanh(v.x);
        w1s[(k4 + 1) * W1P + h] = xla_tanh(v.y);
        w1s[(k4 + 2) * W1P + h] = xla_tanh(v.z);
        w1s[(k4 + 3) * W1P + h] = xla_tanh(v.w);
    }
    for (int idx = tid; idx < 128 * 32; idx += 512) {
        int s = idx >> 5;
        int k4 = (idx & 31) << 2;
        float4 v = make_float4(0.f, 0.f, 0.f, 0.f);
        if (b0 + s < B) v = *(const float4*)&x[(size_t)(b0 + s) * IDIM + k4];
        float* d = &xs[s * XP + k4];
        d[0] = norm_x(v.x);
        d[1] = norm_x(v.y);
        d[2] = norm_x(v.z);
        d[3] = norm_x(v.w);
    }
    __syncthreads();

    int tx = tid & 15;   // sample group: s = tx + 16*i, i in 0..7
    int ty = tid >> 4;   // h group: h = ty*8 + {0..7} as 4 pairs

    unsigned long long acc2[8][4];
#pragma unroll
    for (int i = 0; i < 8; ++i)
#pragma unroll
        for (int jp = 0; jp < 4; ++jp) acc2[i][jp] = 0ull;

#pragma unroll 1
    for (int k4 = 0; k4 < 32; ++k4) {
        float4 a4[8];
#pragma unroll
        for (int i = 0; i < 8; ++i)
            a4[i] = *(const float4*)&xs[(tx + 16 * i) * XP + k4 * 4];
#pragma unroll
        for (int kk = 0; kk < 4; ++kk) {
            int k = k4 * 4 + kk;
            const ulonglong2* bp = (const ulonglong2*)&w1s[k * W1P + ty * 8];
            ulonglong2 bv0 = bp[0];
            ulonglong2 bv1 = bp[1];
            unsigned long long bb[4] = {bv0.x, bv0.y, bv1.x, bv1.y};
#pragma unroll
            for (int i = 0; i < 8; ++i) {
                const float* ap = &a4[i].x;
                unsigned long long ad = dup2(ap[kk]);
#pragma unroll
                for (int jp = 0; jp < 4; ++jp)
                    fma2(acc2[i][jp], ad, bb[jp]);
            }
        }
    }

    // mem1 recursion (predicated form, confirmed exact)
#pragma unroll
    for (int i = 0; i < 8; ++i) {
        int b = b0 + tx + 16 * i;
#pragma unroll
        for (int jp = 0; jp < 4; ++jp) {
            float2 cc = unpack2(acc2[i][jp]);
#pragma unroll
            for (int half = 0; half < 2; ++half) {
                float c = half ? cc.y : cc.x;
                float mem = 0.0f;
                unsigned msk = 0u;
                bool p = false;
                for (int t = 0; t < T; ++t) {
                    mem = __fmaf_rn(0.95f, mem, c);
                    if (p) mem = __fsub_rn(mem, 1.0f);
                    p = (mem > 1.0f);
                    if (p) msk |= 1u << t;
                }
                if (b < B) {
                    int h = ty * 8 + 2 * jp + half;
                    g_masks[(size_t)h * B + b] = msk;
                }
            }
        }
    }
}

// ---------------------------------------------------------------------------
// Phase 2: o-split 2-way (outputs 0-7 / 8-15 per thread pair — independent
// sums, exact). Ascending-h accumulation via PREDICATED packed FMA (fma pipe);
// 5 passes of 6 steps; next-h mask prefetch; mem2 recursion; spike output.
// ---------------------------------------------------------------------------
__global__ void __launch_bounds__(128, 6) phase2_kernel(const float* __restrict__ w2,
                                                        int T, int B,
                                                        float* __restrict__ out) {
    __shared__ unsigned long long w2s[HDIM * 8];
    int tid = threadIdx.x;
    for (int j = tid; j < HDIM * 8; j += 128) {
        int h = j >> 3, op = j & 7;
        float lo = xla_tanh(w2[(2 * op) * HDIM + h]);
        float hi = xla_tanh(w2[(2 * op + 1) * HDIM + h]);
        w2s[j] = ((unsigned long long)__float_as_uint(hi) << 32)
               | (unsigned long long)__float_as_uint(lo);
    }
    __syncthreads();

    int pid = blockIdx.x * 128 + tid;
    int b = pid >> 1;
    int osel = pid & 1;        // 0: outputs 0-7, 1: outputs 8-15
    if (b >= B) return;

    const unsigned long long ONE2 = 0x3f8000003f800000ULL;

    float mem2[8];
#pragma unroll
    for (int o = 0; o < 8; ++o) mem2[o] = 0.0f;

    int NG = (T + 5) / 6;
    for (int g = 0; g < NG; ++g) {
        unsigned long long acc[6][4];
#pragma unroll
        for (int t = 0; t < 6; ++t)
#pragma unroll
            for (int op = 0; op < 4; ++op) acc[t][op] = 0ull;

        int shift = g * 6;
        const unsigned* mp = g_masks + b;
        unsigned m = (*mp) >> shift;
        mp += B;
        for (int h = 0; h < HDIM; ++h) {
            unsigned mn = (*mp) >> shift;   // prefetch next h (padded row at h=255)
            mp += B;
            const ulonglong2* wp = (const ulonglong2*)&w2s[h * 8 + osel * 4];
            ulonglong2 wv0 = wp[0];
            ulonglong2 wv1 = wp[1];
#pragma unroll
            for (int t = 0; t < 6; ++t) {
                unsigned bit = m & (1u << t);
                PFMA4(acc[t][0], acc[t][1], acc[t][2], acc[t][3],
                      wv0.x, wv0.y, wv1.x, wv1.y, ONE2, bit);
            }
            m = mn;
        }

        // mem2 recursion + output for the 6 steps of this pass
#pragma unroll
        for (int tt = 0; tt < 6; ++tt) {
            int t = g * 6 + tt;
            if (t >= T) break;
            float4 o4[2];
            float* ov = (float*)o4;
#pragma unroll
            for (int op = 0; op < 4; ++op) {
                float2 c = unpack2(acc[tt][op]);
                int o0 = 2 * op;
                float r0 = (mem2[o0] > 1.0f) ? 1.0f : 0.0f;
                mem2[o0] = leaky_update(mem2[o0], c.x, r0);
                ov[o0] = (mem2[o0] > 1.0f) ? 1.0f : 0.0f;
                float r1 = (mem2[o0 + 1] > 1.0f) ? 1.0f : 0.0f;
                mem2[o0 + 1] = leaky_update(mem2[o0 + 1], c.y, r1);
                ov[o0 + 1] = (mem2[o0 + 1] > 1.0f) ? 1.0f : 0.0f;
            }
            float4* dst = (float4*)(out + ((size_t)t * B + b) * ODIM + osel * 8);
            dst[0] = o4[0];
            dst[1] = o4[1];
        }
    }
}

// ---------------------------------------------------------------------------
// Launch
// ---------------------------------------------------------------------------
extern "C" void kernel_launch(void* const* d_in, const int* in_sizes, int n_in,
                              void* d_out, int out_size) {
    if (n_in < 3) return;
    const float* x  = (const float*)d_in[0];
    const float* w1 = (const float*)d_in[1];
    const float* w2 = (const float*)d_in[2];

    int B = in_sizes[0] / IDIM;
    if (B > MAXB) B = MAXB;
    int T = out_size / (B * ODIM);
    if (T > 32) T = 32;
    if (T < 1) T = 1;

    cudaFuncSetAttribute(phase1_kernel, cudaFuncAttributeMaxDynamicSharedMemorySize,
                         P1_SMEM_BYTES);
    phase1_kernel<<<(B + 127) / 128, 512, P1_SMEM_BYTES>>>(x, w1, B, T);

    phase2_kernel<<<(2 * B + 127) / 128, 128>>>(w2, T, B, (float*)d_out);
}

// round 17
// speedup vs baseline: 1.3134x; 1.3134x over previous
#include <cuda_runtime.h>
#include <cstdint>

#define IDIM 128
#define HDIM 256
#define ODIM 16
#define MAXB 65536

// Dense 30-bit spike masks, [h][b]; padded one h-row for phase2 prefetch.
__device__ unsigned g_masks[(size_t)(HDIM + 1) * MAXB];

// ---------------------------------------------------------------------------
// XLA EmitFastTanh, ptxas-contracted (confirmed bit-exact R12-R15).
// ---------------------------------------------------------------------------
__device__ __forceinline__ float xla_tanh(float x) {
    const float kClamp = 7.90531110763549805f;
    float ax = fabsf(x);
    float xc = fmaxf(-kClamp, fminf(kClamp, x));
    float x2 = __fmul_rn(xc, xc);
    float p = __fmaf_rn(x2, -2.76076847742355e-16f, 2.00018790482477e-13f);
    p = __fmaf_rn(x2, p, -8.60467152213735e-11f);
    p = __fmaf_rn(x2, p, 5.12229709037114e-08f);
    p = __fmaf_rn(x2, p, 1.48572235717979e-05f);
    p = __fmaf_rn(x2, p, 6.37261928875436e-04f);
    p = __fmaf_rn(x2, p, 4.89352455891786e-03f);
    float num = __fmul_rn(xc, p);
    float q = __fmaf_rn(x2, 1.19825839466702e-06f, 1.18534705686654e-04f);
    q = __fmaf_rn(x2, q, 2.26843463243900e-03f);
    q = __fmaf_rn(x2, q, 4.89352518554385e-03f);
    float r = __fdiv_rn(num, q);
    return (ax < 0.0004f) ? x : r;
}

__device__ __forceinline__ float leaky_update(float mem, float c, float r) {
    return __fsub_rn(__fmaf_rn(0.95f, mem, c), r);
}

__device__ __forceinline__ float norm_x(float v) {
    const float kRecip3 = 1.0f / 3.0f;
    return __fmul_rn(fminf(3.0f, fmaxf(-3.0f, v)), kRecip3);
}

__device__ __forceinline__ void fma2(unsigned long long& d, unsigned long long a,
                                     unsigned long long b) {
    asm("fma.rn.f32x2 %0, %1, %2, %0;" : "+l"(d) : "l"(a), "l"(b));
}
__device__ __forceinline__ unsigned long long dup2(float a) {
    unsigned long long r;
    asm("mov.b64 %0, {%1, %1};" : "=l"(r) : "f"(a));
    return r;
}
__device__ __forceinline__ unsigned long long pack2u(unsigned a) {
    unsigned long long r;
    asm("mov.b64 %0, {%1, %1};" : "=l"(r) : "r"(a));
    return r;
}
__device__ __forceinline__ float2 unpack2(unsigned long long v) {
    float2 r;
    asm("mov.b64 {%0, %1}, %2;" : "=f"(r.x), "=f"(r.y) : "l"(v));
    return r;
}

// ---------------------------------------------------------------------------
// Phase 1 (R14 verbatim — proven bit-exact): tanh(w1)->smem transposed;
// cur1 GEMM (f32x2 h-pairs, per-lane ascending-k fma); mem1 -> dense masks.
// ---------------------------------------------------------------------------
#define W1P 260
#define XP  132
#define P1_SMEM_BYTES ((128 * W1P + 128 * XP) * 4)   // 200704 B

__global__ void __launch_bounds__(512, 1) phase1_kernel(const float* __restrict__ x,
                                                        const float* __restrict__ w1,
                                                        int B, int T) {
    extern __shared__ float sm[];
    float* w1s = sm;                    // [k][h], pitch W1P
    float* xs  = sm + 128 * W1P;        // [s][k], pitch XP
    int tid = threadIdx.x;
    int b0 = blockIdx.x * 128;

    for (int idx = tid; idx < (HDIM * IDIM) / 4; idx += 512) {
        int h = idx >> 5;
        int k4 = (idx & 31) << 2;
        float4 v = *(const float4*)&w1[h * IDIM + k4];
        w1s[(k4 + 0) * W1P + h] = xla_tanh(v.x);
        w1s[(k4 + 1) * W1P + h] = xla_tanh(v.y);
        w1s[(k4 + 2) * W1P + h] = xla_tanh(v.z);
        w1s[(k4 + 3) * W1P + h] = xla_tanh(v.w);
    }
    for (int idx = tid; idx < 128 * 32; idx += 512) {
        int s = idx >> 5;
        int k4 = (idx & 31) << 2;
        float4 v = make_float4(0.f, 0.f, 0.f, 0.f);
        if (b0 + s < B) v = *(const float4*)&x[(size_t)(b0 + s) * IDIM + k4];
        float* d = &xs[s * XP + k4];
        d[0] = norm_x(v.x);
        d[1] = norm_x(v.y);
        d[2] = norm_x(v.z);
        d[3] = norm_x(v.w);
    }
    __syncthreads();

    int tx = tid & 15;
    int ty = tid >> 4;

    unsigned long long acc2[8][4];
#pragma unroll
    for (int i = 0; i < 8; ++i)
#pragma unroll
        for (int jp = 0; jp < 4; ++jp) acc2[i][jp] = 0ull;

#pragma unroll 1
    for (int k4 = 0; k4 < 32; ++k4) {
        float4 a4[8];
#pragma unroll
        for (int i = 0; i < 8; ++i)
            a4[i] = *(const float4*)&xs[(tx + 16 * i) * XP + k4 * 4];
#pragma unroll
        for (int kk = 0; kk < 4; ++kk) {
            int k = k4 * 4 + kk;
            const ulonglong2* bp = (const ulonglong2*)&w1s[k * W1P + ty * 8];
            ulonglong2 bv0 = bp[0];
            ulonglong2 bv1 = bp[1];
            unsigned long long bb[4] = {bv0.x, bv0.y, bv1.x, bv1.y};
#pragma unroll
            for (int i = 0; i < 8; ++i) {
                const float* ap = &a4[i].x;
                unsigned long long ad = dup2(ap[kk]);
#pragma unroll
                for (int jp = 0; jp < 4; ++jp)
                    fma2(acc2[i][jp], ad, bb[jp]);
            }
        }
    }

#pragma unroll
    for (int i = 0; i < 8; ++i) {
        int b = b0 + tx + 16 * i;
#pragma unroll
        for (int jp = 0; jp < 4; ++jp) {
            float2 cc = unpack2(acc2[i][jp]);
#pragma unroll
            for (int half = 0; half < 2; ++half) {
                float c = half ? cc.y : cc.x;
                float mem = 0.0f;
                unsigned msk = 0u;
                bool p = false;
                for (int t = 0; t < T; ++t) {
                    mem = __fmaf_rn(0.95f, mem, c);
                    if (p) mem = __fsub_rn(mem, 1.0f);
                    p = (mem > 1.0f);
                    if (p) msk |= 1u << t;
                }
                if (b < B) {
                    int h = ty * 8 + 2 * jp + half;
                    g_masks[(size_t)h * B + b] = msk;
                }
            }
        }
    }
}

// ---------------------------------------------------------------------------
// Phase 2: full-16-output threads (amortize decode over 8 FFMA2).
// Weights pre-scaled by 2^126 (exact). Spike multiplier = single-bit extract
// (mg << (23-tt)) & 0x00800000 -> exactly 2^-126 or +0; fma internal product
// (w*2^126)*(2^-126) = w exactly -> rn(w+acc), bit-identical to reference
// ascending-h serial sum; +0 case never changes acc. Groups of 5 steps.
// ---------------------------------------------------------------------------
__global__ void __launch_bounds__(128, 4) phase2_kernel(const float* __restrict__ w2,
                                                        int T, int B,
                                                        float* __restrict__ out) {
    __shared__ unsigned long long w2s[HDIM * 8];
    int tid = threadIdx.x;
    const float kScale = 8.507059173023462e37f;   // 2^126, exact in fp32
    for (int j = tid; j < HDIM * 8; j += 128) {
        int h = j >> 3, op = j & 7;
        float lo = __fmul_rn(xla_tanh(w2[(2 * op) * HDIM + h]), kScale);      // exact
        float hi = __fmul_rn(xla_tanh(w2[(2 * op + 1) * HDIM + h]), kScale);  // exact
        w2s[j] = ((unsigned long long)__float_as_uint(hi) << 32)
               | (unsigned long long)__float_as_uint(lo);
    }
    __syncthreads();

    int b = blockIdx.x * 128 + tid;
    if (b >= B) return;

    const unsigned KBIT = 0x00800000u;   // 2^-126 when bit lands at 23

    float mem2[ODIM];
#pragma unroll
    for (int o = 0; o < ODIM; ++o) mem2[o] = 0.0f;

    int NG = (T + 4) / 5;
    for (int g = 0; g < NG; ++g) {
        unsigned long long acc[5][8];
#pragma unroll
        for (int t = 0; t < 5; ++t)
#pragma unroll
            for (int op = 0; op < 8; ++op) acc[t][op] = 0ull;

        int shift = g * 5;
        const unsigned* mp = g_masks + b;
        unsigned mw = *mp;
        mp += B;
        for (int h = 0; h < HDIM; ++h) {
            unsigned mn = *mp;          // prefetch next h (padded row at h=255)
            mp += B;
            unsigned mg = mw >> shift;
            const ulonglong2* wp = (const ulonglong2*)&w2s[h * 8];
            ulonglong2 wv0 = wp[0];
            ulonglong2 wv1 = wp[1];
            ulonglong2 wv2 = wp[2];
            ulonglong2 wv3 = wp[3];
#pragma unroll
            for (int tt = 0; tt < 5; ++tt) {
                unsigned sp32 = (mg << (23 - tt)) & KBIT;
                unsigned long long sp = pack2u(sp32);
                fma2(acc[tt][0], wv0.x, sp);
                fma2(acc[tt][1], wv0.y, sp);
                fma2(acc[tt][2], wv1.x, sp);
                fma2(acc[tt][3], wv1.y, sp);
                fma2(acc[tt][4], wv2.x, sp);
                fma2(acc[tt][5], wv2.y, sp);
                fma2(acc[tt][6], wv3.x, sp);
                fma2(acc[tt][7], wv3.y, sp);
            }
            mw = mn;
        }

        // mem2 recursion + output for the 5 steps of this pass
#pragma unroll
        for (int tt = 0; tt < 5; ++tt) {
            int t = g * 5 + tt;
            if (t >= T) break;
            float4 o4[4];
            float* ov = (float*)o4;
#pragma unroll
            for (int op = 0; op < 8; ++op) {
                float2 c = unpack2(acc[tt][op]);
                int o0 = 2 * op;
                float r0 = (mem2[o0] > 1.0f) ? 1.0f : 0.0f;
                mem2[o0] = leaky_update(mem2[o0], c.x, r0);
                ov[o0] = (mem2[o0] > 1.0f) ? 1.0f : 0.0f;
                float r1 = (mem2[o0 + 1] > 1.0f) ? 1.0f : 0.0f;
                mem2[o0 + 1] = leaky_update(mem2[o0 + 1], c.y, r1);
                ov[o0 + 1] = (mem2[o0 + 1] > 1.0f) ? 1.0f : 0.0f;
            }
            float4* dst = (float4*)(out + ((size_t)t * B + b) * ODIM);
            dst[0] = o4[0];
            dst[1] = o4[1];
            dst[2] = o4[2];
            dst[3] = o4[3];
        }
    }
}

// ---------------------------------------------------------------------------
// Launch
// ---------------------------------------------------------------------------
extern "C" void kernel_launch(void* const* d_in, const int* in_sizes, int n_in,
                              void* d_out, int out_size) {
    if (n_in < 3) return;
    const float* x  = (const float*)d_in[0];
    const float* w1 = (const float*)d_in[1];
    const float* w2 = (const float*)d_in[2];

    int B = in_sizes[0] / IDIM;
    if (B > MAXB) B = MAXB;
    int T = out_size / (B * ODIM);
    if (T > 32) T = 32;
    if (T < 1) T = 1;

    cudaFuncSetAttribute(phase1_kernel, cudaFuncAttributeMaxDynamicSharedMemorySize,
                         P1_SMEM_BYTES);
    phase1_kernel<<<(B + 127) / 128, 512, P1_SMEM_BYTES>>>(x, w1, B, T);

    phase2_kernel<<<(B + 127) / 128, 128>>>(w2, T, B, (float*)d_out);
}